// round 8
// baseline (speedup 1.0000x reference)
#include <cuda_runtime.h>
#include <cuda_bf16.h>
#include <mma.h>
#include <cstdint>

using namespace nvcuda;

#define GEXP 16
#define DDIM 512
#define BMAX 4096
#define TILEM 128
#define MAXTILES (BMAX / TILEM + GEXP)
#define KCH 16
#define NCHUNK (DDIM / KCH)           // 32
#define LDA 24                        // A smem row: 16 + 8 pad bf16 = 48 B
#define LDB 136                       // B smem row: 128 + 8 pad bf16 = 272 B
#define SA_MAT 6144                   // 128*24*2
#define SB_MAT 4608                   // 16*136*2 = 4352, padded
#define OFF_AL 6144
#define OFF_BH 12288
#define OFF_BL 16896
#define STAGE_BYTES 21504
#define SMEM_TOTAL (4 * STAGE_BYTES)  // 86016; f32 staging 128*132*4=67584 fits
#define LDS_F32 132

// ---------------- device scratch (static; no allocations allowed) ----------
__device__ int g_offsets[GEXP + 1];
__device__ int g_perm[BMAX];
__device__ int g_tile_expert[MAXTILES];
__device__ int g_tile_row[MAXTILES];
__device__ int g_num_tiles;

// bf16 hi/lo weights, SAME layout as W: [mat][g][d][h]  (h contiguous)
__device__ __nv_bfloat16 g_W_hi[4][GEXP * DDIM * DDIM];
__device__ __nv_bfloat16 g_W_lo[4][GEXP * DDIM * DDIM];
// features split (original token order)
__device__ __nv_bfloat16 g_A_hi[BMAX * DDIM];
__device__ __nv_bfloat16 g_A_lo[BMAX * DDIM];
// layer-0 hidden split, permuted token order, [branch]
__device__ __nv_bfloat16 g_H_hi[2][BMAX * DDIM];
__device__ __nv_bfloat16 g_H_lo[2][BMAX * DDIM];

// ---------------- helpers ---------------------------------------------------
__device__ __forceinline__ uint32_t smem_u32(const void* p) {
    uint32_t a;
    asm("{ .reg .u64 t; cvta.to.shared.u64 t, %1; cvt.u32.u64 %0, t; }" : "=r"(a) : "l"(p));
    return a;
}

__device__ __forceinline__ void cp16(uint32_t dst, const void* src) {
    size_t gsrc = (size_t)__cvta_generic_to_global(src);
    asm volatile("cp.async.cg.shared.global [%0], [%1], 16;" :: "r"(dst), "l"(gsrc) : "memory");
}

// ---------------------------------------------------------------------------
// Setup: dtype-detect goal (parallel), histogram, offsets, perm, tile list.
// ---------------------------------------------------------------------------
__global__ void setup_kernel(const void* __restrict__ goal_raw, int B)
{
    __shared__ int s_cnt[GEXP];
    __shared__ int s_off[GEXP + 1];
    __shared__ int s_fill[GEXP];
    __shared__ int s_ok;

    int t = threadIdx.x;
    if (t < GEXP) { s_cnt[t] = 0; s_fill[t] = 0; }
    if (t == 0) s_ok = 1;
    __syncthreads();
    if (t < 32) {
        // If buffer is int32, int64 words contain a random goal in the high
        // half -> out of range almost surely for at least one of 32 words.
        long long v = ((const long long*)goal_raw)[t];
        if (v < 0 || v >= GEXP) atomicExch(&s_ok, 0);
    }
    __syncthreads();
    const int is64 = s_ok;

    for (int i = t; i < B; i += blockDim.x) {
        int g = is64 ? (int)((const long long*)goal_raw)[i]
                     : ((const int*)goal_raw)[i];
        atomicAdd(&s_cnt[g], 1);
    }
    __syncthreads();

    if (t == 0) {
        int acc = 0, nt = 0;
        for (int g = 0; g < GEXP; g++) {
            s_off[g] = acc;
            for (int r = 0; r < s_cnt[g]; r += TILEM) {
                g_tile_expert[nt] = g;
                g_tile_row[nt]    = acc + r;
                nt++;
            }
            acc += s_cnt[g];
        }
        s_off[GEXP] = acc;
        g_num_tiles = nt;
        for (int g = 0; g <= GEXP; g++) g_offsets[g] = s_off[g];
    }
    __syncthreads();

    for (int i = t; i < B; i += blockDim.x) {
        int g = is64 ? (int)((const long long*)goal_raw)[i]
                     : ((const int*)goal_raw)[i];
        int pos = s_off[g] + atomicAdd(&s_fill[g], 1);
        g_perm[pos] = i;
    }
}

// ---------------------------------------------------------------------------
// Streaming converts: fp32 -> bf16 hi/lo, identity layout (no transpose).
// ---------------------------------------------------------------------------
__global__ void convert_w_kernel(
    const float* __restrict__ Wp0, const float* __restrict__ Wp1,
    const float* __restrict__ Wv0, const float* __restrict__ Wv1)
{
    const int NW2 = GEXP * DDIM * DDIM / 2;   // float2 pairs per matrix
    for (long long idx = blockIdx.x * (long long)blockDim.x + threadIdx.x;
         idx < 4LL * NW2; idx += gridDim.x * (long long)blockDim.x) {
        int mat = (int)(idx / NW2);
        int rem = (int)(idx - (long long)mat * NW2);
        const float* W = (mat == 0) ? Wp0 : (mat == 1) ? Wp1 : (mat == 2) ? Wv0 : Wv1;
        float2 v = *(const float2*)(W + (size_t)rem * 2);
        __nv_bfloat16 h0 = __float2bfloat16(v.x);
        __nv_bfloat16 h1 = __float2bfloat16(v.y);
        __nv_bfloat16 l0 = __float2bfloat16(v.x - __bfloat162float(h0));
        __nv_bfloat16 l1 = __float2bfloat16(v.y - __bfloat162float(h1));
        *(__nv_bfloat162*)(g_W_hi[mat] + (size_t)rem * 2) = __halves2bfloat162(h0, h1);
        *(__nv_bfloat162*)(g_W_lo[mat] + (size_t)rem * 2) = __halves2bfloat162(l0, l1);
    }
}

__global__ void convert_f_kernel(const float* __restrict__ X, int n2)
{
    for (int i = blockIdx.x * blockDim.x + threadIdx.x; i < n2;
         i += gridDim.x * blockDim.x) {
        float2 v = *(const float2*)(X + (size_t)i * 2);
        __nv_bfloat16 h0 = __float2bfloat16(v.x);
        __nv_bfloat16 h1 = __float2bfloat16(v.y);
        __nv_bfloat16 l0 = __float2bfloat16(v.x - __bfloat162float(h0));
        __nv_bfloat16 l1 = __float2bfloat16(v.y - __bfloat162float(h1));
        *(__nv_bfloat162*)(g_A_hi + (size_t)i * 2) = __halves2bfloat162(h0, h1);
        *(__nv_bfloat162*)(g_A_lo + (size_t)i * 2) = __halves2bfloat162(l0, l1);
    }
}

// ---------------------------------------------------------------------------
// Grouped GEMM layer via WMMA (HMMA), 4-stage cp.async ring, KCH=16,
// ONE barrier per chunk. B used row-major [k][n] directly from W layout.
// 3-term bf16 split: Ah*Bh + Ah*Bl + Al*Bh, fp32 accumulate.
// blockIdx: x = M-tile, y = N-tile (0..3), z = branch.
// ---------------------------------------------------------------------------
#define LOAD_CHUNK(S)                                                          \
    do {                                                                       \
        const uint32_t _b = sbase + ((S) & 3) * STAGE_BYTES;                   \
        if (arow >= 0) {                                                       \
            cp16(_b + soffA,          pah + (S) * KCH);                        \
            cp16(_b + OFF_AL + soffA, pal + (S) * KCH);                        \
        }                                                                      \
        cp16(_b + soffB,                    pbh + (size_t)(S) * KCH * DDIM);   \
        cp16(_b + (OFF_BL - OFF_BH) + soffB, pbl + (size_t)(S) * KCH * DDIM);  \
    } while (0)

__global__ __launch_bounds__(256, 2)
void gemm_layer(const float* __restrict__ bias_pi, const float* __restrict__ bias_vf,
                float* __restrict__ out, int layer, int B)
{
    const int tile = blockIdx.x;
    if (tile >= g_num_tiles) return;
    const int g    = g_tile_expert[tile];
    const int row0 = g_tile_row[tile];
    int rows = g_offsets[g + 1] - row0;
    if (rows > TILEM) rows = TILEM;
    const int n0 = blockIdx.y * 128;
    const int z  = blockIdx.z;
    const int mat = z * 2 + layer;

    extern __shared__ char smem[];
    const uint32_t sbase = smem_u32(smem);

    const int tid = threadIdx.x;
    const int wid = tid >> 5;

    const __nv_bfloat16* Ah = (layer == 0) ? g_A_hi : g_H_hi[z];
    const __nv_bfloat16* Al = (layer == 0) ? g_A_lo : g_H_lo[z];
    const __nv_bfloat16* Wh = g_W_hi[mat] + (size_t)g * DDIM * DDIM;
    const __nv_bfloat16* Wl = g_W_lo[mat] + (size_t)g * DDIM * DDIM;

    // A loader: 2 threads per row, 8 bf16 (16B) each
    const int r    = tid >> 1;
    const int half = tid & 1;
    const uint32_t soffA = (uint32_t)(r * 48 + half * 16);

    int arow = -1;
    if (r < rows) arow = (layer == 0) ? g_perm[row0 + r] : (row0 + r);
    const __nv_bfloat16* pah = (arow >= 0) ? (Ah + (size_t)arow * DDIM + half * 8) : nullptr;
    const __nv_bfloat16* pal = (arow >= 0) ? (Al + (size_t)arow * DDIM + half * 8) : nullptr;

    // B loader: 16 threads per k-row, 8 bf16 each; tile rows k, cols n0..n0+127
    const int kb = tid >> 4;            // 0..15
    const int nb = (tid & 15) * 8;      // 0..120
    const uint32_t soffB = (uint32_t)(OFF_BH + kb * 272 + (tid & 15) * 16);
    const __nv_bfloat16* pbh = Wh + (size_t)kb * DDIM + n0 + nb;
    const __nv_bfloat16* pbl = Wl + (size_t)kb * DDIM + n0 + nb;

    // zero invalid A rows in all 4 stages (cp.async never writes them)
    if (arow < 0) {
        float4 zz = make_float4(0.f, 0.f, 0.f, 0.f);
        #pragma unroll
        for (int st = 0; st < 4; st++) {
            char* p = smem + st * STAGE_BYTES + soffA;
            *(float4*)(p)          = zz;
            *(float4*)(p + OFF_AL) = zz;
        }
    }

    // warp tile: 32 rows x 64 cols
    const int wm0 = (wid & 3) * 32;
    const int wn0 = (wid >> 2) * 64;

    wmma::fragment<wmma::accumulator, 16, 16, 16, float> acc[2][4];
    #pragma unroll
    for (int i = 0; i < 2; i++)
        #pragma unroll
        for (int j = 0; j < 4; j++)
            wmma::fill_fragment(acc[i][j], 0.0f);

    // prologue: stages 0..2 in flight
    LOAD_CHUNK(0);
    asm volatile("cp.async.commit_group;" ::: "memory");
    LOAD_CHUNK(1);
    asm volatile("cp.async.commit_group;" ::: "memory");
    LOAD_CHUNK(2);
    asm volatile("cp.async.commit_group;" ::: "memory");

    #pragma unroll 1
    for (int s = 0; s < NCHUNK; s++) {
        asm volatile("cp.async.wait_group 2;" ::: "memory");  // chunk s resident
        __syncthreads();                                       // ...for all warps
        if (s + 3 < NCHUNK) LOAD_CHUNK(s + 3);                 // overwrites s-1: safe
        asm volatile("cp.async.commit_group;" ::: "memory");   // constant accounting

        const char* st = smem + (s & 3) * STAGE_BYTES;
        const __nv_bfloat16* As_hi = (const __nv_bfloat16*)(st);
        const __nv_bfloat16* As_lo = (const __nv_bfloat16*)(st + OFF_AL);
        const __nv_bfloat16* Bs_hi = (const __nv_bfloat16*)(st + OFF_BH);
        const __nv_bfloat16* Bs_lo = (const __nv_bfloat16*)(st + OFF_BL);

        wmma::fragment<wmma::matrix_a, 16, 16, 16, __nv_bfloat16, wmma::row_major> fa0, fa1, fl0, fl1;
        wmma::load_matrix_sync(fa0, As_hi + (wm0 +  0) * LDA, LDA);
        wmma::load_matrix_sync(fa1, As_hi + (wm0 + 16) * LDA, LDA);
        wmma::load_matrix_sync(fl0, As_lo + (wm0 +  0) * LDA, LDA);
        wmma::load_matrix_sync(fl1, As_lo + (wm0 + 16) * LDA, LDA);

        #pragma unroll
        for (int j = 0; j < 4; j++) {
            wmma::fragment<wmma::matrix_b, 16, 16, 16, __nv_bfloat16, wmma::row_major> fb;
            wmma::load_matrix_sync(fb, Bs_hi + wn0 + j * 16, LDB);
            wmma::mma_sync(acc[0][j], fa0, fb, acc[0][j]);
            wmma::mma_sync(acc[1][j], fa1, fb, acc[1][j]);
            wmma::mma_sync(acc[0][j], fl0, fb, acc[0][j]);
            wmma::mma_sync(acc[1][j], fl1, fb, acc[1][j]);
            wmma::load_matrix_sync(fb, Bs_lo + wn0 + j * 16, LDB);
            wmma::mma_sync(acc[0][j], fa0, fb, acc[0][j]);
            wmma::mma_sync(acc[1][j], fa1, fb, acc[1][j]);
        }
    }

    __syncthreads();   // all compute done before staging overwrites operand smem

    // ---- stage accumulators to smem f32 ----
    float* stage = (float*)smem;
    #pragma unroll
    for (int i = 0; i < 2; i++)
        #pragma unroll
        for (int j = 0; j < 4; j++)
            wmma::store_matrix_sync(stage + (wm0 + i * 16) * LDS_F32 + wn0 + j * 16,
                                    acc[i][j], LDS_F32, wmma::mem_row_major);
    __syncthreads();

    // ---- epilogue: bias + tanh ----
    const int m     = tid >> 1;
    const int cbase = (tid & 1) * 64;
    if (m < rows) {
        const float* bias = ((z == 0) ? bias_pi : bias_vf) + g * DDIM + n0 + cbase;
        const float* srow = stage + m * LDS_F32 + cbase;
        const int prow = row0 + m;
        if (layer == 0) {
            __nv_bfloat16* OH = g_H_hi[z] + (size_t)prow * DDIM + n0 + cbase;
            __nv_bfloat16* OL = g_H_lo[z] + (size_t)prow * DDIM + n0 + cbase;
            #pragma unroll
            for (int c = 0; c < 64; c += 2) {
                float v0 = tanhf(srow[c]     + __ldg(bias + c));
                float v1 = tanhf(srow[c + 1] + __ldg(bias + c + 1));
                __nv_bfloat16 h0 = __float2bfloat16(v0);
                __nv_bfloat16 h1 = __float2bfloat16(v1);
                __nv_bfloat16 l0 = __float2bfloat16(v0 - __bfloat162float(h0));
                __nv_bfloat16 l1 = __float2bfloat16(v1 - __bfloat162float(h1));
                *(__nv_bfloat162*)(OH + c) = __halves2bfloat162(h0, h1);
                *(__nv_bfloat162*)(OL + c) = __halves2bfloat162(l0, l1);
            }
        } else {
            int orow = g_perm[prow];
            float* OF = out + ((size_t)z * B + orow) * DDIM + n0 + cbase;
            #pragma unroll
            for (int c = 0; c < 64; c += 4) {
                float4 o;
                o.x = tanhf(srow[c]     + __ldg(bias + c));
                o.y = tanhf(srow[c + 1] + __ldg(bias + c + 1));
                o.z = tanhf(srow[c + 2] + __ldg(bias + c + 2));
                o.w = tanhf(srow[c + 3] + __ldg(bias + c + 3));
                *(float4*)(OF + c) = o;
            }
        }
    }
}

// ---------------------------------------------------------------------------
extern "C" void kernel_launch(void* const* d_in, const int* in_sizes, int n_in,
                              void* d_out, int out_size)
{
    const float* features = (const float*)d_in[0];
    const float* Wp0 = (const float*)d_in[1];
    const float* bp0 = (const float*)d_in[2];
    const float* Wp1 = (const float*)d_in[3];
    const float* bp1 = (const float*)d_in[4];
    const float* Wv0 = (const float*)d_in[5];
    const float* bv0 = (const float*)d_in[6];
    const float* Wv1 = (const float*)d_in[7];
    const float* bv1 = (const float*)d_in[8];
    const void*  goal = d_in[9];

    int B = in_sizes[0] / DDIM;
    if (B > BMAX) B = BMAX;

    cudaFuncSetAttribute(gemm_layer, cudaFuncAttributeMaxDynamicSharedMemorySize, SMEM_TOTAL);

    setup_kernel<<<1, 1024>>>(goal, B);
    convert_w_kernel<<<2048, 256>>>(Wp0, Wp1, Wv0, Wv1);
    convert_f_kernel<<<512, 256>>>(features, B * DDIM / 2);

    dim3 gg(B / TILEM + GEXP, 4, 2);
    gemm_layer<<<gg, 256, SMEM_TOTAL>>>(bp0, bv0, nullptr, 0, B);
    gemm_layer<<<gg, 256, SMEM_TOTAL>>>(bp1, bv1, (float*)d_out, 1, B);
}

// round 12
// speedup vs baseline: 1.0591x; 1.0591x over previous
#include <cuda_runtime.h>
#include <cuda_bf16.h>
#include <mma.h>
#include <cstdint>

using namespace nvcuda;

#define GEXP 16
#define DDIM 512
#define BMAX 4096
#define TILEM 64
#define MAXTILES (BMAX / TILEM + GEXP)
#define KCH 16
#define NCHUNK (DDIM / KCH)           // 32
#define LDA 24                        // A smem row: 16 + 8 pad bf16 = 48 B
#define LDB 136                       // B smem row: 128 + 8 pad bf16 = 272 B
#define OFF_AL 3072                   // A hi: 64*48 = 3072
#define OFF_BH 6144
#define OFF_BL 10496                  // B mat: 16*272 = 4352
#define STAGE_BYTES 14848
#define NSTAGE 4
#define SMEM_TOTAL (NSTAGE * STAGE_BYTES)  // 59392; f32 staging 64*132*4=33792 fits
#define LDS_F32 132

// ---------------- device scratch (static; no allocations allowed) ----------
__device__ int g_offsets[GEXP + 1];
__device__ int g_perm[BMAX];
__device__ int g_tile_expert[MAXTILES];
__device__ int g_tile_row[MAXTILES];
__device__ int g_num_tiles;

// bf16 hi/lo weights, SAME layout as W: [mat][g][d][h]  (h contiguous)
__device__ __nv_bfloat16 g_W_hi[4][GEXP * DDIM * DDIM];
__device__ __nv_bfloat16 g_W_lo[4][GEXP * DDIM * DDIM];
// features split (original token order)
__device__ __nv_bfloat16 g_A_hi[BMAX * DDIM];
__device__ __nv_bfloat16 g_A_lo[BMAX * DDIM];
// layer-0 hidden split, permuted token order, [branch]
__device__ __nv_bfloat16 g_H_hi[2][BMAX * DDIM];
__device__ __nv_bfloat16 g_H_lo[2][BMAX * DDIM];

// ---------------- helpers ---------------------------------------------------
__device__ __forceinline__ uint32_t smem_u32(const void* p) {
    uint32_t a;
    asm("{ .reg .u64 t; cvta.to.shared.u64 t, %1; cvt.u32.u64 %0, t; }" : "=r"(a) : "l"(p));
    return a;
}

__device__ __forceinline__ void cp16(uint32_t dst, const void* src) {
    size_t gsrc = (size_t)__cvta_generic_to_global(src);
    asm volatile("cp.async.cg.shared.global [%0], [%1], 16;" :: "r"(dst), "l"(gsrc) : "memory");
}

// ---------------------------------------------------------------------------
// Setup: dtype-detect goal (parallel), histogram, offsets, perm, tile list.
// ---------------------------------------------------------------------------
__global__ void setup_kernel(const void* __restrict__ goal_raw, int B)
{
    __shared__ int s_cnt[GEXP];
    __shared__ int s_off[GEXP + 1];
    __shared__ int s_fill[GEXP];
    __shared__ int s_ok;

    int t = threadIdx.x;
    if (t < GEXP) { s_cnt[t] = 0; s_fill[t] = 0; }
    if (t == 0) s_ok = 1;
    __syncthreads();
    if (t < 32) {
        long long v = ((const long long*)goal_raw)[t];
        if (v < 0 || v >= GEXP) atomicExch(&s_ok, 0);
    }
    __syncthreads();
    const int is64 = s_ok;

    for (int i = t; i < B; i += blockDim.x) {
        int g = is64 ? (int)((const long long*)goal_raw)[i]
                     : ((const int*)goal_raw)[i];
        atomicAdd(&s_cnt[g], 1);
    }
    __syncthreads();

    if (t == 0) {
        int acc = 0, nt = 0;
        for (int g = 0; g < GEXP; g++) {
            s_off[g] = acc;
            for (int r = 0; r < s_cnt[g]; r += TILEM) {
                g_tile_expert[nt] = g;
                g_tile_row[nt]    = acc + r;
                nt++;
            }
            acc += s_cnt[g];
        }
        s_off[GEXP] = acc;
        g_num_tiles = nt;
        for (int g = 0; g <= GEXP; g++) g_offsets[g] = s_off[g];
    }
    __syncthreads();

    for (int i = t; i < B; i += blockDim.x) {
        int g = is64 ? (int)((const long long*)goal_raw)[i]
                     : ((const int*)goal_raw)[i];
        int pos = s_off[g] + atomicAdd(&s_fill[g], 1);
        g_perm[pos] = i;
    }
}

// ---------------------------------------------------------------------------
// Streaming converts: fp32 -> bf16 hi/lo, identity layout (no transpose).
// ---------------------------------------------------------------------------
__global__ void convert_w_kernel(
    const float* __restrict__ Wp0, const float* __restrict__ Wp1,
    const float* __restrict__ Wv0, const float* __restrict__ Wv1)
{
    const int NW2 = GEXP * DDIM * DDIM / 2;
    for (long long idx = blockIdx.x * (long long)blockDim.x + threadIdx.x;
         idx < 4LL * NW2; idx += gridDim.x * (long long)blockDim.x) {
        int mat = (int)(idx / NW2);
        int rem = (int)(idx - (long long)mat * NW2);
        const float* W = (mat == 0) ? Wp0 : (mat == 1) ? Wp1 : (mat == 2) ? Wv0 : Wv1;
        float2 v = *(const float2*)(W + (size_t)rem * 2);
        __nv_bfloat16 h0 = __float2bfloat16(v.x);
        __nv_bfloat16 h1 = __float2bfloat16(v.y);
        __nv_bfloat16 l0 = __float2bfloat16(v.x - __bfloat162float(h0));
        __nv_bfloat16 l1 = __float2bfloat16(v.y - __bfloat162float(h1));
        *(__nv_bfloat162*)(g_W_hi[mat] + (size_t)rem * 2) = __halves2bfloat162(h0, h1);
        *(__nv_bfloat162*)(g_W_lo[mat] + (size_t)rem * 2) = __halves2bfloat162(l0, l1);
    }
}

__global__ void convert_f_kernel(const float* __restrict__ X, int n2)
{
    for (int i = blockIdx.x * blockDim.x + threadIdx.x; i < n2;
         i += gridDim.x * blockDim.x) {
        float2 v = *(const float2*)(X + (size_t)i * 2);
        __nv_bfloat16 h0 = __float2bfloat16(v.x);
        __nv_bfloat16 h1 = __float2bfloat16(v.y);
        __nv_bfloat16 l0 = __float2bfloat16(v.x - __bfloat162float(h0));
        __nv_bfloat16 l1 = __float2bfloat16(v.y - __bfloat162float(h1));
        *(__nv_bfloat162*)(g_A_hi + (size_t)i * 2) = __halves2bfloat162(h0, h1);
        *(__nv_bfloat162*)(g_A_lo + (size_t)i * 2) = __halves2bfloat162(l0, l1);
    }
}

// ---------------------------------------------------------------------------
// Grouped GEMM via WMMA: CTA tile 64x128 (8 warps, warp tile 16x64, acc=32
// regs/thread), 4-stage cp.async ring, one barrier per chunk, 3 CTAs/SM.
// 3-term bf16 split: Ah*Bh + Ah*Bl + Al*Bh, fp32 accumulate.
// blockIdx: x = M-tile, y = N-tile (0..3), z = branch.
// ---------------------------------------------------------------------------
#define LOAD_CHUNK(S)                                                          \
    do {                                                                       \
        const uint32_t _b = sbase + ((S) & (NSTAGE - 1)) * STAGE_BYTES;        \
        if (arow >= 0) cp16(_b + soffA, paA + (S) * KCH);                      \
        cp16(_b + OFF_BH + soffB, pbh + (size_t)(S) * KCH * DDIM);             \
        cp16(_b + OFF_BL + soffB, pbl + (size_t)(S) * KCH * DDIM);             \
    } while (0)

__global__ __launch_bounds__(256, 3)
void gemm_layer(const float* __restrict__ bias_pi, const float* __restrict__ bias_vf,
                float* __restrict__ out, int layer, int B)
{
    const int tile = blockIdx.x;
    if (tile >= g_num_tiles) return;
    const int g    = g_tile_expert[tile];
    const int row0 = g_tile_row[tile];
    int rows = g_offsets[g + 1] - row0;
    if (rows > TILEM) rows = TILEM;
    const int n0 = blockIdx.y * 128;
    const int z  = blockIdx.z;
    const int mat = z * 2 + layer;

    extern __shared__ char smem[];
    const uint32_t sbase = smem_u32(smem);

    const int tid = threadIdx.x;
    const int wid = tid >> 5;

    const __nv_bfloat16* Ah = (layer == 0) ? g_A_hi : g_H_hi[z];
    const __nv_bfloat16* Al = (layer == 0) ? g_A_lo : g_H_lo[z];
    const __nv_bfloat16* Wh = g_W_hi[mat] + (size_t)g * DDIM * DDIM;
    const __nv_bfloat16* Wl = g_W_lo[mat] + (size_t)g * DDIM * DDIM;

    // A loader: 4 threads per row (hi/lo x 2 halves), 8 bf16 (16B) each
    const int r    = tid >> 2;          // 0..63
    const int q    = tid & 3;           // 0,1: hi; 2,3: lo
    const uint32_t soffA = (uint32_t)(r * 48 + (q & 1) * 16 + (q >> 1) * OFF_AL);

    int arow = -1;
    if (r < rows) arow = (layer == 0) ? g_perm[row0 + r] : (row0 + r);
    const __nv_bfloat16* paA = nullptr;
    if (arow >= 0)
        paA = ((q >> 1) ? Al : Ah) + (size_t)arow * DDIM + (q & 1) * 8;

    // B loader: 16 threads per k-row, 8 bf16 each (hi + lo per thread)
    const int kb = tid >> 4;            // 0..15
    const uint32_t soffB = (uint32_t)(kb * 272 + (tid & 15) * 16);
    const __nv_bfloat16* pbh = Wh + (size_t)kb * DDIM + n0 + (tid & 15) * 8;
    const __nv_bfloat16* pbl = Wl + (size_t)kb * DDIM + n0 + (tid & 15) * 8;

    // zero invalid A slots in all stages (cp.async never writes them)
    if (arow < 0) {
        float4 zz = make_float4(0.f, 0.f, 0.f, 0.f);
        #pragma unroll
        for (int st = 0; st < NSTAGE; st++)
            *(float4*)(smem + st * STAGE_BYTES + soffA) = zz;
    }

    // warp tile: 16 rows x 64 cols
    const int wm0 = (wid & 3) * 16;
    const int wn0 = (wid >> 2) * 64;

    wmma::fragment<wmma::accumulator, 16, 16, 16, float> acc[4];
    #pragma unroll
    for (int j = 0; j < 4; j++) wmma::fill_fragment(acc[j], 0.0f);

    // prologue: stages 0..2 in flight
    LOAD_CHUNK(0);
    asm volatile("cp.async.commit_group;" ::: "memory");
    LOAD_CHUNK(1);
    asm volatile("cp.async.commit_group;" ::: "memory");
    LOAD_CHUNK(2);
    asm volatile("cp.async.commit_group;" ::: "memory");

    #pragma unroll 1
    for (int s = 0; s < NCHUNK; s++) {
        asm volatile("cp.async.wait_group 2;" ::: "memory");  // chunk s resident
        __syncthreads();
        if (s + 3 < NCHUNK) LOAD_CHUNK(s + 3);                 // overwrites s-1: safe
        asm volatile("cp.async.commit_group;" ::: "memory");

        const char* st = smem + (s & (NSTAGE - 1)) * STAGE_BYTES;
        const __nv_bfloat16* As_hi = (const __nv_bfloat16*)(st);
        const __nv_bfloat16* As_lo = (const __nv_bfloat16*)(st + OFF_AL);
        const __nv_bfloat16* Bs_hi = (const __nv_bfloat16*)(st + OFF_BH);
        const __nv_bfloat16* Bs_lo = (const __nv_bfloat16*)(st + OFF_BL);

        wmma::fragment<wmma::matrix_a, 16, 16, 16, __nv_bfloat16, wmma::row_major> fa, fl;
        wmma::load_matrix_sync(fa, As_hi + wm0 * LDA, LDA);
        wmma::load_matrix_sync(fl, As_lo + wm0 * LDA, LDA);

        #pragma unroll
        for (int j = 0; j < 4; j++) {
            wmma::fragment<wmma::matrix_b, 16, 16, 16, __nv_bfloat16, wmma::row_major> fb;
            wmma::load_matrix_sync(fb, Bs_hi + wn0 + j * 16, LDB);
            wmma::mma_sync(acc[j], fa, fb, acc[j]);
            wmma::mma_sync(acc[j], fl, fb, acc[j]);
            wmma::load_matrix_sync(fb, Bs_lo + wn0 + j * 16, LDB);
            wmma::mma_sync(acc[j], fa, fb, acc[j]);
        }
    }

    __syncthreads();   // all compute done before staging overwrites operand smem

    // ---- stage accumulators to smem f32 ----
    float* stage = (float*)smem;
    #pragma unroll
    for (int j = 0; j < 4; j++)
        wmma::store_matrix_sync(stage + wm0 * LDS_F32 + wn0 + j * 16,
                                acc[j], LDS_F32, wmma::mem_row_major);
    __syncthreads();

    // ---- epilogue: bias + tanh ----
    const int m     = tid >> 2;          // 0..63
    const int cbase = (tid & 3) * 32;    // 0,32,64,96
    if (m < rows) {
        const float* bias = ((z == 0) ? bias_pi : bias_vf) + g * DDIM + n0 + cbase;
        const float* srow = stage + m * LDS_F32 + cbase;
        const int prow = row0 + m;
        if (layer == 0) {
            __nv_bfloat16* OH = g_H_hi[z] + (size_t)prow * DDIM + n0 + cbase;
            __nv_bfloat16* OL = g_H_lo[z] + (size_t)prow * DDIM + n0 + cbase;
            #pragma unroll
            for (int c = 0; c < 32; c += 2) {
                float v0 = tanhf(srow[c]     + __ldg(bias + c));
                float v1 = tanhf(srow[c + 1] + __ldg(bias + c + 1));
                __nv_bfloat16 h0 = __float2bfloat16(v0);
                __nv_bfloat16 h1 = __float2bfloat16(v1);
                __nv_bfloat16 l0 = __float2bfloat16(v0 - __bfloat162float(h0));
                __nv_bfloat16 l1 = __float2bfloat16(v1 - __bfloat162float(h1));
                *(__nv_bfloat162*)(OH + c) = __halves2bfloat162(h0, h1);
                *(__nv_bfloat162*)(OL + c) = __halves2bfloat162(l0, l1);
            }
        } else {
            int orow = g_perm[prow];
            float* OF = out + ((size_t)z * B + orow) * DDIM + n0 + cbase;
            #pragma unroll
            for (int c = 0; c < 32; c += 4) {
                float4 o;
                o.x = tanhf(srow[c]     + __ldg(bias + c));
                o.y = tanhf(srow[c + 1] + __ldg(bias + c + 1));
                o.z = tanhf(srow[c + 2] + __ldg(bias + c + 2));
                o.w = tanhf(srow[c + 3] + __ldg(bias + c + 3));
                *(float4*)(OF + c) = o;
            }
        }
    }
}

// ---------------------------------------------------------------------------
extern "C" void kernel_launch(void* const* d_in, const int* in_sizes, int n_in,
                              void* d_out, int out_size)
{
    const float* features = (const float*)d_in[0];
    const float* Wp0 = (const float*)d_in[1];
    const float* bp0 = (const float*)d_in[2];
    const float* Wp1 = (const float*)d_in[3];
    const float* bp1 = (const float*)d_in[4];
    const float* Wv0 = (const float*)d_in[5];
    const float* bv0 = (const float*)d_in[6];
    const float* Wv1 = (const float*)d_in[7];
    const float* bv1 = (const float*)d_in[8];
    const void*  goal = d_in[9];

    int B = in_sizes[0] / DDIM;
    if (B > BMAX) B = BMAX;

    cudaFuncSetAttribute(gemm_layer, cudaFuncAttributeMaxDynamicSharedMemorySize, SMEM_TOTAL);

    setup_kernel<<<1, 1024>>>(goal, B);
    convert_w_kernel<<<2048, 256>>>(Wp0, Wp1, Wv0, Wv1);
    convert_f_kernel<<<512, 256>>>(features, B * DDIM / 2);

    dim3 gg(B / TILEM + GEXP, 4, 2);
    gemm_layer<<<gg, 256, SMEM_TOTAL>>>(bp0, bv0, nullptr, 0, B);
    gemm_layer<<<gg, 256, SMEM_TOTAL>>>(bp1, bv1, (float*)d_out, 1, B);
}